// round 8
// baseline (speedup 1.0000x reference)
#include <cuda_runtime.h>
#include <cuda_fp16.h>
#include <math.h>

#define NNODES 50000
#define DIM    128
#define NCLS   40
#define EMAX   600000
#define SCAN_B 1024
#define NSB    ((NNODES + SCAN_B - 1) / SCAN_B)   // 49 scan blocks

// ---------------- device scratch (no allocations allowed) ----------------
__device__ int     g_is64;
__device__ int     g_cnt[NNODES];
__device__ int     g_cur[NNODES];
__device__ int     g_off[NNODES + 1];
__device__ unsigned long long g_state[NSB];
__device__ int     g_csr[EMAX];
__device__ float   g_dinv[NNODES];
__device__ __half2 g_hs2[NNODES * (DIM / 2)];    // row-scaled features, fp16
__device__ __half2 g_ag2[NNODES * (DIM / 2)];    // layer-1 aggregation, fp16

// ---------------- setup: zero counters + dtype detect ---------------------
__global__ void k_init(const int* ei) {
    int i = blockIdx.x * blockDim.x + threadIdx.x;
    if (i < NNODES) g_cnt[i] = 0;
    if (i < NSB) g_state[i] = 0ULL;
    if (blockIdx.x == 0 && threadIdx.x == 0) {
        int nz = 0;
        #pragma unroll
        for (int j = 0; j < 16; j++) nz += (ei[2 * j + 1] != 0);
        g_is64 = (nz == 0) ? 1 : 0;
    }
}

__global__ void k_cnt(const void* ei, long long E) {
    long long base = ((long long)blockIdx.x * blockDim.x + threadIdx.x) * 2;
    if (base >= E) return;
    int d0, d1; bool two = (base + 1 < E);
    if (g_is64) {
        const long long* pd = (const long long*)ei + E;
        if (two) {
            longlong2 v = *(const longlong2*)&pd[base];
            d0 = (int)v.x; d1 = (int)v.y;
        } else d0 = (int)pd[base];
    } else {
        const int* pd = (const int*)ei + (size_t)E;
        if (two) {
            int2 v = *(const int2*)&pd[base];
            d0 = v.x; d1 = v.y;
        } else d0 = pd[base];
    }
    atomicAdd(&g_cnt[d0], 1);
    if (two) atomicAdd(&g_cnt[d1], 1);
}

// ---------------- one-pass decoupled-lookback scan (+dinv, +cursors) ------
__global__ void __launch_bounds__(SCAN_B) k_scan() {
    __shared__ int wsum[32];
    __shared__ int s_run;
    const int tid = threadIdx.x, lane = tid & 31, wid = tid >> 5;
    const int bid = blockIdx.x;
    const int i = bid * SCAN_B + tid;

    int v = (i < NNODES) ? g_cnt[i] : 0;
    if (i < NNODES) g_dinv[i] = rsqrtf((float)(v + 1));

    int incl = v;
    #pragma unroll
    for (int s = 1; s < 32; s <<= 1) {
        int t = __shfl_up_sync(0xffffffffu, incl, s);
        if (lane >= s) incl += t;
    }
    if (lane == 31) wsum[wid] = incl;
    __syncthreads();
    if (wid == 0) {
        int w = wsum[lane];
        int wi = w;
        #pragma unroll
        for (int s = 1; s < 32; s <<= 1) {
            int t = __shfl_up_sync(0xffffffffu, wi, s);
            if (lane >= s) wi += t;
        }
        wsum[lane] = wi - w;
    }
    __syncthreads();
    int excl = incl - v + wsum[wid];

    if (tid == SCAN_B - 1) {
        int total = excl + v;
        long long run = 0;
        if (bid == 0) {
            atomicExch(&g_state[0], (2ULL << 32) | (unsigned)total);
        } else {
            atomicExch(&g_state[bid], (1ULL << 32) | (unsigned)total);
            int p = bid - 1;
            while (true) {
                unsigned long long st = atomicAdd(&g_state[p], 0ULL);
                unsigned f = (unsigned)(st >> 32);
                if (f == 2u) { run += (int)(unsigned)st; break; }
                if (f == 1u) { run += (int)(unsigned)st; --p; continue; }
                __nanosleep(20);
            }
            atomicExch(&g_state[bid], (2ULL << 32) | (unsigned)(run + total));
        }
        s_run = (int)run;
        if (bid == NSB - 1) g_off[NNODES] = (int)run + total;
    }
    __syncthreads();
    if (i < NNODES) {
        int o = excl + s_run;
        g_off[i] = o;
        g_cur[i] = o;
    }
}

__global__ void k_fill(const void* ei, long long E) {
    long long base = ((long long)blockIdx.x * blockDim.x + threadIdx.x) * 2;
    if (base >= E) return;
    int s0, s1, d0, d1; bool two = (base + 1 < E);
    if (g_is64) {
        const long long* ps = (const long long*)ei;
        const long long* pd = ps + E;
        if (two) {
            longlong2 vs = *(const longlong2*)&ps[base];
            longlong2 vd = *(const longlong2*)&pd[base];
            s0 = (int)vs.x; s1 = (int)vs.y; d0 = (int)vd.x; d1 = (int)vd.y;
        } else { s0 = (int)ps[base]; d0 = (int)pd[base]; }
    } else {
        const int* ps = (const int*)ei;
        const int* pd = ps + (size_t)E;
        if (two) {
            int2 vs = *(const int2*)&ps[base];
            int2 vd = *(const int2*)&pd[base];
            s0 = vs.x; s1 = vs.y; d0 = vd.x; d1 = vd.y;
        } else { s0 = ps[base]; d0 = pd[base]; }
    }
    int p0 = atomicAdd(&g_cur[d0], 1);
    int p1 = two ? atomicAdd(&g_cur[d1], 1) : 0;
    g_csr[p0] = s0;
    if (two) g_csr[p1] = s1;
}

// ---------------- tensor-core GEMM (swizzled, 64-row tile) ----------------
// block: 64 rows x 128 cols, 8 warps in 4x2 (warp = 16 rows x 64 cols)
// smem: A 64x256B (16KB) + W 128x256B (32KB) = 48KB, XOR-swizzled, no pad.
#define A_BYTES (64 * 256)
#define GEMM_SMEM (A_BYTES + 128 * 256)

__device__ __forceinline__ unsigned sw_off(int r, int chunk) {
    return (unsigned)(r * 256 + ((chunk ^ (r & 7)) << 4));
}

__global__ void __launch_bounds__(256, 4) k_gemm(const float* __restrict__ x,
                                                 const float* __restrict__ W,
                                                 const float* __restrict__ bias,
                                                 int mode) {
    extern __shared__ char smc[];
    char* Asb = smc;             // A tile, swizzled
    char* Wsb = smc + A_BYTES;   // W tile, swizzled
    const int tid = threadIdx.x;
    const int r0  = blockIdx.x * 64;

    // stage W -> fp16 swizzled (128 rows x 128 halves)
    #pragma unroll
    for (int j = 0; j < 16; j++) {
        int flat = (tid + j * 256) * 4;       // half index
        int c = flat >> 7, k = flat & 127;
        float4 w = *(const float4*)&W[c * 128 + k];
        uint2 u;
        *(__half2*)&u.x = __floats2half2_rn(w.x, w.y);
        *(__half2*)&u.y = __floats2half2_rn(w.z, w.w);
        *(uint2*)(Wsb + sw_off(c, k >> 3) + ((k & 7) << 1)) = u;
    }
    // stage A -> fp16 swizzled (64 rows x 128 halves)
    #pragma unroll
    for (int j = 0; j < 8; j++) {
        int flat = (tid + j * 256) * 4;
        int rl = flat >> 7, k = flat & 127;
        int r = r0 + rl;
        float4 v = make_float4(0.f, 0.f, 0.f, 0.f);
        if (r < NNODES) {
            if (mode == 0) {
                v = *(const float4*)&x[(size_t)r * DIM + k];
            } else {
                uint2 u = *(const uint2*)&g_ag2[(size_t)r * 64 + (k >> 1)];
                float2 a0 = __half22float2(*(const __half2*)&u.x);
                float2 a1 = __half22float2(*(const __half2*)&u.y);
                float4 b = *(const float4*)&bias[k];
                float di = g_dinv[r];
                v.x = fmaxf(fmaf(a0.x, di, b.x), 0.f);
                v.y = fmaxf(fmaf(a0.y, di, b.y), 0.f);
                v.z = fmaxf(fmaf(a1.x, di, b.z), 0.f);
                v.w = fmaxf(fmaf(a1.y, di, b.w), 0.f);
            }
        }
        uint2 u;
        *(__half2*)&u.x = __floats2half2_rn(v.x, v.y);
        *(__half2*)&u.y = __floats2half2_rn(v.z, v.w);
        *(uint2*)(Asb + sw_off(rl, k >> 3) + ((k & 7) << 1)) = u;
    }
    __syncthreads();

    const int warp = tid >> 5, lane = tid & 31;
    const int m0 = (warp >> 1) * 16;     // row base within tile
    const int n0 = (warp & 1) * 64;      // col base within tile
    const int gid = lane >> 2, tig = lane & 3;

    float acc[8][4];
    #pragma unroll
    for (int t = 0; t < 8; t++)
        #pragma unroll
        for (int q = 0; q < 4; q++) acc[t][q] = 0.f;

    unsigned aSm = (unsigned)__cvta_generic_to_shared(Asb);
    unsigned wSm = (unsigned)__cvta_generic_to_shared(Wsb);
    const int aRow = m0 + (lane & 15);
    const int aChA = (lane & 16) ? 1 : 0;
    const int bRow = ((lane & 16) ? 8 : 0) + (lane & 7);
    const int bChA = (lane & 8) ? 1 : 0;

    #pragma unroll
    for (int ks = 0; ks < 8; ks++) {
        unsigned a0, a1, a2, a3;
        unsigned aAddr = aSm + sw_off(aRow, 2 * ks + aChA);
        asm volatile("ldmatrix.sync.aligned.m8n8.x4.shared.b16 {%0,%1,%2,%3},[%4];"
                     : "=r"(a0), "=r"(a1), "=r"(a2), "=r"(a3) : "r"(aAddr));
        #pragma unroll
        for (int tp = 0; tp < 4; tp++) {
            unsigned b0, b1, b2, b3;
            unsigned bAddr = wSm + sw_off(n0 + 16 * tp + bRow, 2 * ks + bChA);
            asm volatile("ldmatrix.sync.aligned.m8n8.x4.shared.b16 {%0,%1,%2,%3},[%4];"
                         : "=r"(b0), "=r"(b1), "=r"(b2), "=r"(b3) : "r"(bAddr));
            asm volatile("mma.sync.aligned.m16n8k16.row.col.f32.f16.f16.f32 "
                         "{%0,%1,%2,%3},{%4,%5,%6,%7},{%8,%9},{%0,%1,%2,%3};"
                         : "+f"(acc[2 * tp][0]), "+f"(acc[2 * tp][1]),
                           "+f"(acc[2 * tp][2]), "+f"(acc[2 * tp][3])
                         : "r"(a0), "r"(a1), "r"(a2), "r"(a3), "r"(b0), "r"(b1));
            asm volatile("mma.sync.aligned.m16n8k16.row.col.f32.f16.f16.f32 "
                         "{%0,%1,%2,%3},{%4,%5,%6,%7},{%8,%9},{%0,%1,%2,%3};"
                         : "+f"(acc[2 * tp + 1][0]), "+f"(acc[2 * tp + 1][1]),
                           "+f"(acc[2 * tp + 1][2]), "+f"(acc[2 * tp + 1][3])
                         : "r"(a0), "r"(a1), "r"(a2), "r"(a3), "r"(b2), "r"(b3));
        }
    }

    // epilogue: rows r1=r0+m0+gid, r2=r1+8; cols n0 + 8t + 2tig(+1)
    const int r1 = r0 + m0 + gid;
    const int r2 = r1 + 8;
    const float d1 = (r1 < NNODES) ? g_dinv[r1] : 0.f;
    const float d2 = (r2 < NNODES) ? g_dinv[r2] : 0.f;
    #pragma unroll
    for (int t = 0; t < 8; t++) {
        int ci = (n0 >> 1) + 4 * t + tig;
        if (r1 < NNODES)
            g_hs2[(size_t)r1 * 64 + ci] =
                __floats2half2_rn(acc[t][0] * d1, acc[t][1] * d1);
        if (r2 < NNODES)
            g_hs2[(size_t)r2 * 64 + ci] =
                __floats2half2_rn(acc[t][2] * d2, acc[t][3] * d2);
    }
}

// ---------------- gather-aggregate (warp per node, fp16 reads) ------------
__device__ __forceinline__ void acc_row(float4& acc, const __half2* row) {
    uint2 u = __ldg((const uint2*)row);
    float2 f0 = __half22float2(*(const __half2*)&u.x);
    float2 f1 = __half22float2(*(const __half2*)&u.y);
    acc.x += f0.x; acc.y += f0.y; acc.z += f1.x; acc.w += f1.y;
}

template <bool FUSE_HEAD>
__global__ void __launch_bounds__(256) k_agg(const float* __restrict__ b2,
                                             const float* __restrict__ Wl,
                                             const float* __restrict__ bl,
                                             float* __restrict__ out) {
    __shared__ float Wls[NCLS * DIM];
    __shared__ float bls[NCLS];
    const int tid  = threadIdx.x;
    const int lane = tid & 31;

    if (FUSE_HEAD) {
        #pragma unroll
        for (int j = 0; j < 5; j++) {
            int i4 = tid + j * 256;
            if (i4 < NCLS * DIM / 4)
                ((float4*)Wls)[i4] = ((const float4*)Wl)[i4];
        }
        if (tid < NCLS) bls[tid] = bl[tid];
        __syncthreads();
    }

    const int r = (blockIdx.x * 256 + tid) >> 5;
    if (r >= NNODES) return;

    const int beg = g_off[r], end = g_off[r + 1];
    float4 acc = make_float4(0.f, 0.f, 0.f, 0.f);
    acc_row(acc, &g_hs2[(size_t)r * 64 + lane * 2]);   // self-loop

    int j = beg;
    for (; j + 8 <= end; j += 8) {
        int sx[8];
        #pragma unroll
        for (int q = 0; q < 8; q++) sx[q] = __ldg(&g_csr[j + q]);
        #pragma unroll
        for (int q = 0; q < 8; q++)
            acc_row(acc, &g_hs2[(size_t)sx[q] * 64 + lane * 2]);
    }
    for (; j + 4 <= end; j += 4) {
        int sx[4];
        #pragma unroll
        for (int q = 0; q < 4; q++) sx[q] = __ldg(&g_csr[j + q]);
        #pragma unroll
        for (int q = 0; q < 4; q++)
            acc_row(acc, &g_hs2[(size_t)sx[q] * 64 + lane * 2]);
    }
    for (; j < end; ++j)
        acc_row(acc, &g_hs2[(size_t)__ldg(&g_csr[j]) * 64 + lane * 2]);

    if (!FUSE_HEAD) {
        uint2 o;
        *(__half2*)&o.x = __floats2half2_rn(acc.x, acc.y);
        *(__half2*)&o.y = __floats2half2_rn(acc.z, acc.w);
        *(uint2*)&g_ag2[(size_t)r * 64 + lane * 2] = o;
        return;
    }

    const float di = g_dinv[r];
    float4 bv = *(const float4*)&b2[lane * 4];
    float4 v;
    v.x = fmaxf(fmaf(acc.x, di, bv.x), 0.f);
    v.y = fmaxf(fmaf(acc.y, di, bv.y), 0.f);
    v.z = fmaxf(fmaf(acc.z, di, bv.z), 0.f);
    v.w = fmaxf(fmaf(acc.w, di, bv.w), 0.f);

    float ml0 = 0.f, ml1 = -1e30f;
    #pragma unroll
    for (int c = 0; c < NCLS; c++) {
        float4 w = *(const float4*)&Wls[c * DIM + lane * 4];
        float p = v.x * w.x + v.y * w.y + v.z * w.z + v.w * w.w;
        #pragma unroll
        for (int s = 16; s > 0; s >>= 1)
            p += __shfl_xor_sync(0xffffffffu, p, s);
        p += bls[c];
        if (c < 32) { if (lane == c)      ml0 = p; }
        else        { if (lane == c - 32) ml1 = p; }
    }

    float m = fmaxf(ml0, ml1);
    #pragma unroll
    for (int s = 16; s > 0; s >>= 1)
        m = fmaxf(m, __shfl_xor_sync(0xffffffffu, m, s));
    float e = __expf(ml0 - m) + ((lane < 8) ? __expf(ml1 - m) : 0.f);
    #pragma unroll
    for (int s = 16; s > 0; s >>= 1)
        e += __shfl_xor_sync(0xffffffffu, e, s);
    float ls = __logf(e);

    out[(size_t)r * NCLS + lane] = ml0 - m - ls;
    if (lane < 8)
        out[(size_t)r * NCLS + 32 + lane] = ml1 - m - ls;
}

// ---------------- launch ---------------------------------------------------
extern "C" void kernel_launch(void* const* d_in, const int* in_sizes, int n_in,
                              void* d_out, int out_size) {
    const float* x  = (const float*)d_in[0];
    const void*  ei = d_in[1];
    const float* W1 = (const float*)d_in[2];
    const float* b1 = (const float*)d_in[3];
    const float* W2 = (const float*)d_in[4];
    const float* b2 = (const float*)d_in[5];
    const float* Wl = (const float*)d_in[6];
    const float* bl = (const float*)d_in[7];
    float* out = (float*)d_out;

    const long long E = in_sizes[1] / 2;

    cudaFuncSetAttribute(k_gemm, cudaFuncAttributeMaxDynamicSharedMemorySize,
                         GEMM_SMEM);

    const int NB_N    = (NNODES + 255) / 256;
    const int NB_E2   = (int)((E + 511) / 512);
    const int NB_GEMM = (NNODES + 63) / 64;
    const int NB_AGG  = (NNODES * 32 + 255) / 256;

    k_init<<<NB_N, 256>>>((const int*)ei);
    k_cnt<<<NB_E2, 256>>>(ei, E);
    k_scan<<<NSB, SCAN_B>>>();
    // gemm1 in profiled slot 4
    k_gemm<<<NB_GEMM, 256, GEMM_SMEM>>>(x, W1, b1, 0);
    k_fill<<<NB_E2, 256>>>(ei, E);

    k_agg<false><<<NB_AGG, 256>>>(nullptr, nullptr, nullptr, nullptr);

    k_gemm<<<NB_GEMM, 256, GEMM_SMEM>>>(x, W2, b1, 1);
    k_agg<true><<<NB_AGG, 256>>>(b2, Wl, bl, out);
}

// round 9
// speedup vs baseline: 1.0030x; 1.0030x over previous
#include <cuda_runtime.h>
#include <cuda_fp16.h>
#include <math.h>

#define NNODES 50000
#define DIM    128
#define NCLS   40
#define EMAX   600000
#define SCAN_B 1024
#define NSB    ((NNODES + SCAN_B - 1) / SCAN_B)

// ---------------- device scratch ------------------------------------------
__device__ int     g_is64;
__device__ int     g_cnt[NNODES];
__device__ int     g_cur[NNODES];
__device__ int     g_off[NNODES + 1];
__device__ unsigned long long g_state[NSB];
__device__ int2    g_csr2[EMAX];                 // {src, bits(dinv[src])}
__device__ float   g_dinv[NNODES];
__device__ __half2 g_hs2[NNODES * (DIM / 2)];    // RAW features h, fp16
__device__ __half2 g_ag2[NNODES * (DIM / 2)];    // layer-1 aggregation, fp16

// ---------------- setup ----------------------------------------------------
__global__ void k_init(const int* ei) {
    int i = blockIdx.x * blockDim.x + threadIdx.x;
    if (i < NNODES) g_cnt[i] = 0;
    if (i < NSB) g_state[i] = 0ULL;
    if (blockIdx.x == 0 && threadIdx.x == 0) {
        int nz = 0;
        #pragma unroll
        for (int j = 0; j < 16; j++) nz += (ei[2 * j + 1] != 0);
        g_is64 = (nz == 0) ? 1 : 0;
    }
}

__global__ void k_cnt(const void* ei, long long E) {
    long long base = ((long long)blockIdx.x * blockDim.x + threadIdx.x) * 2;
    if (base >= E) return;
    int d0, d1; bool two = (base + 1 < E);
    if (g_is64) {
        const long long* pd = (const long long*)ei + E;
        if (two) { longlong2 v = *(const longlong2*)&pd[base]; d0 = (int)v.x; d1 = (int)v.y; }
        else d0 = (int)pd[base];
    } else {
        const int* pd = (const int*)ei + (size_t)E;
        if (two) { int2 v = *(const int2*)&pd[base]; d0 = v.x; d1 = v.y; }
        else d0 = pd[base];
    }
    atomicAdd(&g_cnt[d0], 1);
    if (two) atomicAdd(&g_cnt[d1], 1);
}

// ---------------- one-pass decoupled-lookback scan (+dinv, +cursors) ------
__global__ void __launch_bounds__(SCAN_B) k_scan() {
    __shared__ int wsum[32];
    __shared__ int s_run;
    const int tid = threadIdx.x, lane = tid & 31, wid = tid >> 5;
    const int bid = blockIdx.x;
    const int i = bid * SCAN_B + tid;

    int v = (i < NNODES) ? g_cnt[i] : 0;
    if (i < NNODES) g_dinv[i] = rsqrtf((float)(v + 1));

    int incl = v;
    #pragma unroll
    for (int s = 1; s < 32; s <<= 1) {
        int t = __shfl_up_sync(0xffffffffu, incl, s);
        if (lane >= s) incl += t;
    }
    if (lane == 31) wsum[wid] = incl;
    __syncthreads();
    if (wid == 0) {
        int w = wsum[lane];
        int wi = w;
        #pragma unroll
        for (int s = 1; s < 32; s <<= 1) {
            int t = __shfl_up_sync(0xffffffffu, wi, s);
            if (lane >= s) wi += t;
        }
        wsum[lane] = wi - w;
    }
    __syncthreads();
    int excl = incl - v + wsum[wid];

    if (tid == SCAN_B - 1) {
        int total = excl + v;
        long long run = 0;
        if (bid == 0) {
            atomicExch(&g_state[0], (2ULL << 32) | (unsigned)total);
        } else {
            atomicExch(&g_state[bid], (1ULL << 32) | (unsigned)total);
            int p = bid - 1;
            while (true) {
                unsigned long long st = atomicAdd(&g_state[p], 0ULL);
                unsigned f = (unsigned)(st >> 32);
                if (f == 2u) { run += (int)(unsigned)st; break; }
                if (f == 1u) { run += (int)(unsigned)st; --p; continue; }
                __nanosleep(20);
            }
            atomicExch(&g_state[bid], (2ULL << 32) | (unsigned)(run + total));
        }
        s_run = (int)run;
        if (bid == NSB - 1) g_off[NNODES] = (int)run + total;
    }
    __syncthreads();
    if (i < NNODES) {
        int o = excl + s_run;
        g_off[i] = o;
        g_cur[i] = o;
    }
}

// ---------------- fill body (called from fused kernel) --------------------
__device__ __forceinline__ void fill_body(int bx, const void* ei, long long E) {
    long long base = ((long long)bx * 256 + threadIdx.x) * 2;
    if (base >= E) return;
    int s0, s1, d0, d1; bool two = (base + 1 < E);
    if (g_is64) {
        const long long* ps = (const long long*)ei;
        const long long* pd = ps + E;
        if (two) {
            longlong2 vs = *(const longlong2*)&ps[base];
            longlong2 vd = *(const longlong2*)&pd[base];
            s0 = (int)vs.x; s1 = (int)vs.y; d0 = (int)vd.x; d1 = (int)vd.y;
        } else { s0 = (int)ps[base]; d0 = (int)pd[base]; }
    } else {
        const int* ps = (const int*)ei;
        const int* pd = ps + (size_t)E;
        if (two) {
            int2 vs = *(const int2*)&ps[base];
            int2 vd = *(const int2*)&pd[base];
            s0 = vs.x; s1 = vs.y; d0 = vd.x; d1 = vd.y;
        } else { s0 = ps[base]; d0 = pd[base]; }
    }
    float f0 = __ldg(&g_dinv[s0]);
    float f1 = two ? __ldg(&g_dinv[s1]) : 0.f;
    int p0 = atomicAdd(&g_cur[d0], 1);
    int p1 = two ? atomicAdd(&g_cur[d1], 1) : 0;
    g_csr2[p0] = make_int2(s0, __float_as_int(f0));
    if (two) g_csr2[p1] = make_int2(s1, __float_as_int(f1));
}

// ---------------- tensor-core GEMM body (swizzled, 64-row tile) -----------
// out: g_hs2 = RAW f(A) @ W^T (no dinv scaling)
#define A_BYTES (64 * 256)
#define GEMM_SMEM (A_BYTES + 128 * 256)

__device__ __forceinline__ unsigned sw_off(int r, int chunk) {
    return (unsigned)(r * 256 + ((chunk ^ (r & 7)) << 4));
}

__device__ void gemm_body(int bx, const float* __restrict__ x,
                          const float* __restrict__ W,
                          const float* __restrict__ bias,
                          int mode, char* smc) {
    char* Asb = smc;
    char* Wsb = smc + A_BYTES;
    const int tid = threadIdx.x;
    const int r0  = bx * 64;

    #pragma unroll
    for (int j = 0; j < 16; j++) {
        int flat = (tid + j * 256) * 4;
        int c = flat >> 7, k = flat & 127;
        float4 w = *(const float4*)&W[c * 128 + k];
        uint2 u;
        *(__half2*)&u.x = __floats2half2_rn(w.x, w.y);
        *(__half2*)&u.y = __floats2half2_rn(w.z, w.w);
        *(uint2*)(Wsb + sw_off(c, k >> 3) + ((k & 7) << 1)) = u;
    }
    #pragma unroll
    for (int j = 0; j < 8; j++) {
        int flat = (tid + j * 256) * 4;
        int rl = flat >> 7, k = flat & 127;
        int r = r0 + rl;
        float4 v = make_float4(0.f, 0.f, 0.f, 0.f);
        if (r < NNODES) {
            if (mode == 0) {
                v = *(const float4*)&x[(size_t)r * DIM + k];
            } else {
                uint2 u = *(const uint2*)&g_ag2[(size_t)r * 64 + (k >> 1)];
                float2 a0 = __half22float2(*(const __half2*)&u.x);
                float2 a1 = __half22float2(*(const __half2*)&u.y);
                float4 b = *(const float4*)&bias[k];
                float di = g_dinv[r];
                v.x = fmaxf(fmaf(a0.x, di, b.x), 0.f);
                v.y = fmaxf(fmaf(a0.y, di, b.y), 0.f);
                v.z = fmaxf(fmaf(a1.x, di, b.z), 0.f);
                v.w = fmaxf(fmaf(a1.y, di, b.w), 0.f);
            }
        }
        uint2 u;
        *(__half2*)&u.x = __floats2half2_rn(v.x, v.y);
        *(__half2*)&u.y = __floats2half2_rn(v.z, v.w);
        *(uint2*)(Asb + sw_off(rl, k >> 3) + ((k & 7) << 1)) = u;
    }
    __syncthreads();

    const int warp = tid >> 5, lane = tid & 31;
    const int m0 = (warp >> 1) * 16;
    const int n0 = (warp & 1) * 64;
    const int gid = lane >> 2, tig = lane & 3;

    float acc[8][4];
    #pragma unroll
    for (int t = 0; t < 8; t++)
        #pragma unroll
        for (int q = 0; q < 4; q++) acc[t][q] = 0.f;

    unsigned aSm = (unsigned)__cvta_generic_to_shared(Asb);
    unsigned wSm = (unsigned)__cvta_generic_to_shared(Wsb);
    const int aRow = m0 + (lane & 15);
    const int aChA = (lane & 16) ? 1 : 0;
    const int bRow = ((lane & 16) ? 8 : 0) + (lane & 7);
    const int bChA = (lane & 8) ? 1 : 0;

    #pragma unroll
    for (int ks = 0; ks < 8; ks++) {
        unsigned a0, a1, a2, a3;
        unsigned aAddr = aSm + sw_off(aRow, 2 * ks + aChA);
        asm volatile("ldmatrix.sync.aligned.m8n8.x4.shared.b16 {%0,%1,%2,%3},[%4];"
                     : "=r"(a0), "=r"(a1), "=r"(a2), "=r"(a3) : "r"(aAddr));
        #pragma unroll
        for (int tp = 0; tp < 4; tp++) {
            unsigned b0, b1, b2, b3;
            unsigned bAddr = wSm + sw_off(n0 + 16 * tp + bRow, 2 * ks + bChA);
            asm volatile("ldmatrix.sync.aligned.m8n8.x4.shared.b16 {%0,%1,%2,%3},[%4];"
                         : "=r"(b0), "=r"(b1), "=r"(b2), "=r"(b3) : "r"(bAddr));
            asm volatile("mma.sync.aligned.m16n8k16.row.col.f32.f16.f16.f32 "
                         "{%0,%1,%2,%3},{%4,%5,%6,%7},{%8,%9},{%0,%1,%2,%3};"
                         : "+f"(acc[2 * tp][0]), "+f"(acc[2 * tp][1]),
                           "+f"(acc[2 * tp][2]), "+f"(acc[2 * tp][3])
                         : "r"(a0), "r"(a1), "r"(a2), "r"(a3), "r"(b0), "r"(b1));
            asm volatile("mma.sync.aligned.m16n8k16.row.col.f32.f16.f16.f32 "
                         "{%0,%1,%2,%3},{%4,%5,%6,%7},{%8,%9},{%0,%1,%2,%3};"
                         : "+f"(acc[2 * tp + 1][0]), "+f"(acc[2 * tp + 1][1]),
                           "+f"(acc[2 * tp + 1][2]), "+f"(acc[2 * tp + 1][3])
                         : "r"(a0), "r"(a1), "r"(a2), "r"(a3), "r"(b2), "r"(b3));
        }
    }

    const int r1 = r0 + m0 + gid;
    const int r2 = r1 + 8;
    #pragma unroll
    for (int t = 0; t < 8; t++) {
        int ci = (n0 >> 1) + 4 * t + tig;
        if (r1 < NNODES)
            g_hs2[(size_t)r1 * 64 + ci] = __floats2half2_rn(acc[t][0], acc[t][1]);
        if (r2 < NNODES)
            g_hs2[(size_t)r2 * 64 + ci] = __floats2half2_rn(acc[t][2], acc[t][3]);
    }
}

__global__ void __launch_bounds__(256, 4) k_gemm(const float* __restrict__ x,
                                                 const float* __restrict__ W,
                                                 const float* __restrict__ bias,
                                                 int mode) {
    extern __shared__ char smc[];
    gemm_body(blockIdx.x, x, W, bias, mode, smc);
}

// fused: first nGemm blocks do gemm1 (mode 0), rest do CSR fill
__global__ void __launch_bounds__(256, 4) k_gemm_fill(const float* __restrict__ x,
                                                      const float* __restrict__ W,
                                                      const void* ei, long long E,
                                                      int nGemm) {
    extern __shared__ char smc[];
    if (blockIdx.x < nGemm) gemm_body(blockIdx.x, x, W, nullptr, 0, smc);
    else                    fill_body(blockIdx.x - nGemm, ei, E);
}

// ---------------- gather-aggregate (warp per node, dinv[src]-weighted) ----
__device__ __forceinline__ void acc_row_s(float4& acc, const __half2* row, float s) {
    uint2 u = __ldg((const uint2*)row);
    float2 f0 = __half22float2(*(const __half2*)&u.x);
    float2 f1 = __half22float2(*(const __half2*)&u.y);
    acc.x = fmaf(f0.x, s, acc.x); acc.y = fmaf(f0.y, s, acc.y);
    acc.z = fmaf(f1.x, s, acc.z); acc.w = fmaf(f1.y, s, acc.w);
}

template <bool FUSE_HEAD>
__global__ void __launch_bounds__(256) k_agg(const float* __restrict__ b2,
                                             const float* __restrict__ Wl,
                                             const float* __restrict__ bl,
                                             float* __restrict__ out) {
    __shared__ float Wls[NCLS * DIM];
    __shared__ float bls[NCLS];
    const int tid  = threadIdx.x;
    const int lane = tid & 31;

    if (FUSE_HEAD) {
        #pragma unroll
        for (int j = 0; j < 5; j++) {
            int i4 = tid + j * 256;
            if (i4 < NCLS * DIM / 4)
                ((float4*)Wls)[i4] = ((const float4*)Wl)[i4];
        }
        if (tid < NCLS) bls[tid] = bl[tid];
        __syncthreads();
    }

    const int r = (blockIdx.x * 256 + tid) >> 5;
    if (r >= NNODES) return;

    const int beg = g_off[r], end = g_off[r + 1];
    const float dr = g_dinv[r];
    float4 acc = make_float4(0.f, 0.f, 0.f, 0.f);
    acc_row_s(acc, &g_hs2[(size_t)r * 64 + lane * 2], dr);   // self-loop

    int j = beg;
    for (; j + 8 <= end; j += 8) {
        int2 e[8];
        #pragma unroll
        for (int q = 0; q < 8; q++) e[q] = __ldg(&g_csr2[j + q]);
        #pragma unroll
        for (int q = 0; q < 8; q++)
            acc_row_s(acc, &g_hs2[(size_t)e[q].x * 64 + lane * 2],
                      __int_as_float(e[q].y));
    }
    for (; j + 4 <= end; j += 4) {
        int2 e[4];
        #pragma unroll
        for (int q = 0; q < 4; q++) e[q] = __ldg(&g_csr2[j + q]);
        #pragma unroll
        for (int q = 0; q < 4; q++)
            acc_row_s(acc, &g_hs2[(size_t)e[q].x * 64 + lane * 2],
                      __int_as_float(e[q].y));
    }
    for (; j < end; ++j) {
        int2 e = __ldg(&g_csr2[j]);
        acc_row_s(acc, &g_hs2[(size_t)e.x * 64 + lane * 2], __int_as_float(e.y));
    }

    if (!FUSE_HEAD) {
        uint2 o;
        *(__half2*)&o.x = __floats2half2_rn(acc.x, acc.y);
        *(__half2*)&o.y = __floats2half2_rn(acc.z, acc.w);
        *(uint2*)&g_ag2[(size_t)r * 64 + lane * 2] = o;
        return;
    }

    // ---- fused head: relu(acc*dr + b2) @ Wl^T + bl -> log_softmax ----
    float4 bv = *(const float4*)&b2[lane * 4];
    float4 v;
    v.x = fmaxf(fmaf(acc.x, dr, bv.x), 0.f);
    v.y = fmaxf(fmaf(acc.y, dr, bv.y), 0.f);
    v.z = fmaxf(fmaf(acc.z, dr, bv.z), 0.f);
    v.w = fmaxf(fmaf(acc.w, dr, bv.w), 0.f);

    float ml0 = 0.f, ml1 = -1e30f;
    #pragma unroll
    for (int c = 0; c < NCLS; c++) {
        float4 w = *(const float4*)&Wls[c * DIM + lane * 4];
        float p = v.x * w.x + v.y * w.y + v.z * w.z + v.w * w.w;
        #pragma unroll
        for (int s = 16; s > 0; s >>= 1)
            p += __shfl_xor_sync(0xffffffffu, p, s);
        p += bls[c];
        if (c < 32) { if (lane == c)      ml0 = p; }
        else        { if (lane == c - 32) ml1 = p; }
    }

    float m = fmaxf(ml0, ml1);
    #pragma unroll
    for (int s = 16; s > 0; s >>= 1)
        m = fmaxf(m, __shfl_xor_sync(0xffffffffu, m, s));
    float e = __expf(ml0 - m) + ((lane < 8) ? __expf(ml1 - m) : 0.f);
    #pragma unroll
    for (int s = 16; s > 0; s >>= 1)
        e += __shfl_xor_sync(0xffffffffu, e, s);
    float ls = __logf(e);

    out[(size_t)r * NCLS + lane] = ml0 - m - ls;
    if (lane < 8)
        out[(size_t)r * NCLS + 32 + lane] = ml1 - m - ls;
}

// ---------------- launch ---------------------------------------------------
extern "C" void kernel_launch(void* const* d_in, const int* in_sizes, int n_in,
                              void* d_out, int out_size) {
    const float* x  = (const float*)d_in[0];
    const void*  ei = d_in[1];
    const float* W1 = (const float*)d_in[2];
    const float* b1 = (const float*)d_in[3];
    const float* W2 = (const float*)d_in[4];
    const float* b2 = (const float*)d_in[5];
    const float* Wl = (const float*)d_in[6];
    const float* bl = (const float*)d_in[7];
    float* out = (float*)d_out;

    const long long E = in_sizes[1] / 2;

    cudaFuncSetAttribute(k_gemm, cudaFuncAttributeMaxDynamicSharedMemorySize,
                         GEMM_SMEM);
    cudaFuncSetAttribute(k_gemm_fill, cudaFuncAttributeMaxDynamicSharedMemorySize,
                         GEMM_SMEM);

    const int NB_N    = (NNODES + 255) / 256;
    const int NB_E2   = (int)((E + 511) / 512);
    const int NB_GEMM = (NNODES + 63) / 64;
    const int NB_AGG  = (NNODES * 32 + 255) / 256;

    k_init<<<NB_N, 256>>>((const int*)ei);
    k_cnt<<<NB_E2, 256>>>(ei, E);
    k_scan<<<NSB, SCAN_B>>>();

    // gemm1 (independent of CSR/dinv) fused with CSR fill -> overlap
    k_gemm_fill<<<NB_GEMM + NB_E2, 256, GEMM_SMEM>>>(x, W1, ei, E, NB_GEMM);

    k_agg<false><<<NB_AGG, 256>>>(nullptr, nullptr, nullptr, nullptr);

    k_gemm<<<NB_GEMM, 256, GEMM_SMEM>>>(x, W2, b1, 1);
    k_agg<true><<<NB_AGG, 256>>>(b2, Wl, bl, out);
}